// round 16
// baseline (speedup 1.0000x reference)
#include <cuda_runtime.h>

#define NN 64
#define SS 512
#define DD 512
#define CC 1024
#define GRID 128
#define NTHREADS 512

// dynamic smem layout for k_main (bytes):
//   [0,      67584)   per-warp region: 16 warps x 1056 floats (4224 B)
//                       staging double-buffer [0,1024) floats; partials overlap
//                       (prologue: 2 teams x 2048 floats of GEMM tiles)
//   [67584, 100352)   sW1: 1024 rows x 8 floats        (block's W1 slice)
//   [100352,231424)   sW2dup: 1024 rows x 16 ull       (block's W2 slice, duplicated f32x2)
#define PWS 1056
#define SMEM_MAIN (16 * PWS * 4 + 32768 + 131072)

// ---------------- device scratch (static, no allocations) ----------------
__device__ float g_X[(size_t)NN * SS * DD];   // LN'd masked inputs (64 MB)
__device__ float g_ht[NN * DD];
__device__ float g_inter[NN * CC];
__device__ float g_cont[NN * 4 * DD];
__device__ unsigned g_gcnt[8 * 64];           // 8 group counters, 256B apart
__device__ unsigned g_rcnt;
__device__ unsigned g_sense;

typedef unsigned long long ull;

__device__ __forceinline__ void fma2(ull& d, ull a, ull b) {
    asm("fma.rn.f32x2 %0, %1, %2, %0;" : "+l"(d) : "l"(a), "l"(b));
}
__device__ __forceinline__ ull dup2(float f) {
    ull r; asm("mov.b64 %0, {%1, %1};" : "=l"(r) : "f"(f)); return r;
}
__device__ __forceinline__ float2 unp(ull v) {
    float2 r; asm("mov.b64 {%0, %1}, %2;" : "=f"(r.x), "=f"(r.y) : "l"(v)); return r;
}
__device__ __forceinline__ float sigm(float x) { return 1.f / (1.f + expf(-x)); }
__device__ __forceinline__ float gelu_t(float x) {
    float u = x + 0.044715f * x * x * x;
    return 0.5f * x * (1.f + tanhf(0.7978845608028654f * u));
}
__device__ __forceinline__ float4 ldcg4(const float* p) {
    return __ldcg((const float4*)p);
}

// barrier-state reset before each k_main launch (graph-replay safe)
__global__ void k_reset() {
    for (int i = threadIdx.x; i < 8 * 64; i += 64) g_gcnt[i] = 0;
    if (threadIdx.x == 0) { g_rcnt = 0; g_sense = 0; }
}

// Two-level fence-free global barrier: 16-way group arrive + 8-way root.
// acq_rel RMWs carry ordering; release store of g_sense publishes everything.
__device__ __forceinline__ void gbar(unsigned* barc) {
    __syncthreads();
    unsigned target = ++(*barc);
    if (threadIdx.x == 0) {
        unsigned* gc = &g_gcnt[(blockIdx.x >> 4) * 64];
        unsigned prev;
        asm volatile("atom.acq_rel.gpu.add.u32 %0, [%1], 1;"
                     : "=r"(prev) : "l"(gc) : "memory");
        if (prev == 15) {
            unsigned pr;
            asm volatile("atom.acq_rel.gpu.add.u32 %0, [%1], 1;"
                         : "=r"(pr) : "l"(&g_rcnt) : "memory");
            if (pr == 7) {
#pragma unroll
                for (int g = 0; g < 8; g++)
                    asm volatile("st.relaxed.gpu.u32 [%0], %1;"
                                 :: "l"(&g_gcnt[g * 64]), "r"(0u) : "memory");
                asm volatile("st.relaxed.gpu.u32 [%0], %1;"
                             :: "l"(&g_rcnt), "r"(0u) : "memory");
                asm volatile("st.release.gpu.u32 [%0], %1;"
                             :: "l"(&g_sense), "r"(target) : "memory");
            }
        }
        unsigned s;
        do {
            asm volatile("ld.relaxed.gpu.u32 %0, [%1];"
                         : "=r"(s) : "l"(&g_sense) : "memory");
        } while (s < target);
        asm volatile("ld.acquire.gpu.u32 %0, [%1];"
                     : "=r"(s) : "l"(&g_sense) : "memory");
    }
    __syncthreads();
}

// block sum over 512 threads (16 warps)
__device__ __forceinline__ float bsum512(float v, float* sc) {
    int lane = threadIdx.x & 31, w = threadIdx.x >> 5;
#pragma unroll
    for (int o = 16; o; o >>= 1) v += __shfl_xor_sync(0xffffffffu, v, o);
    if (lane == 0) sc[w] = v;
    __syncthreads();
    if (w == 0) {
        float s = (lane < 16) ? sc[lane] : 0.f;
#pragma unroll
        for (int o = 8; o; o >>= 1) s += __shfl_xor_sync(0xffffffffu, s, o);
        if (lane == 0) sc[16] = s;
    }
    __syncthreads();
    float r = sc[16];
    __syncthreads();
    return r;
}

__global__ void __launch_bounds__(NTHREADS, 1) k_main(
    const float* __restrict__ seq, const float* __restrict__ mask,
    const float* __restrict__ START,
    const float* __restrict__ Wi, const float* __restrict__ bi,
    const float* __restrict__ W1, const float* __restrict__ b1,
    const float* __restrict__ W2, const float* __restrict__ b2,
    const float* __restrict__ lng, const float* __restrict__ lnb,
    float* __restrict__ out)
{
    extern __shared__ char smch[];
    float* const Rall = (float*)smch;                         // 16 x PWS floats
    float* const sW1 = (float*)(smch + 16 * PWS * 4);         // [1024][8]
    ull* const sW2d = (ull*)(smch + 16 * PWS * 4 + 32768);    // [1024][16] dup'd
    __shared__ float scC[32];

    const int tid = threadIdx.x;
    const int lane = tid & 31;
    const int warp = tid >> 5;
    const int b = blockIdx.x;
    unsigned barc = 0;

    const int nA0 = b * 8;
    const int nB0 = b * 16;

    // ---- one-time: weight slices into smem (W2 duplicated as f32x2 pairs) ----
    for (int i = tid; i < CC * 2; i += NTHREADS) {      // sW1: 2048 float4
        int row = i >> 1, half = i & 1;
        *(float4*)(sW1 + (size_t)row * 8 + half * 4) =
            *(const float4*)(W1 + (size_t)row * CC + nA0 + half * 4);
    }
    for (int i = tid; i < CC * 16; i += NTHREADS) {     // sW2dup: 16384 ull
        int row = i >> 4, col = i & 15;
        sW2d[i] = dup2(W2[(size_t)row * (4 * DD) + nB0 + col]);
    }

    // =============== prologue 1: g_X stripe = (seq*mask) @ Wi + bi ===============
    {
        const int team = warp >> 3;
        const int ttid = tid & 255;
        float* const As = (float*)smch + team * 2048;
        float* const Bs = As + 1024;
        const int lm = ttid >> 2, kq = (ttid & 3) * 4;
        const int bk = ttid >> 4, bn = (ttid & 15) * 4;
        const int ty = ttid >> 4, tx = ttid & 15;
        const int barid = team + 1;

        for (int rt = 0; rt < 2; rt++) {
            const int row0 = b * 256 + (team * 2 + rt) * 64;
            const float mval = mask[row0 + lm];
            for (int ct = 0; ct < 8; ct++) {
                const int n0 = ct * 64;
                float acc[4][4];
#pragma unroll
                for (int i = 0; i < 4; i++)
#pragma unroll
                    for (int j = 0; j < 4; j++) acc[i][j] = 0.f;

                for (int kt = 0; kt < DD / 16; kt++) {
                    float4 a = *(const float4*)&seq[(size_t)(row0 + lm) * DD + kt * 16 + kq];
                    As[(kq + 0) * 64 + lm] = a.x * mval;
                    As[(kq + 1) * 64 + lm] = a.y * mval;
                    As[(kq + 2) * 64 + lm] = a.z * mval;
                    As[(kq + 3) * 64 + lm] = a.w * mval;
                    *(float4*)&Bs[bk * 64 + bn] =
                        *(const float4*)&Wi[(size_t)(kt * 16 + bk) * DD + n0 + bn];
                    asm volatile("bar.sync %0, 256;" :: "r"(barid) : "memory");
#pragma unroll
                    for (int k = 0; k < 16; k++) {
                        float4 av = *(const float4*)&As[k * 64 + ty * 4];
                        float4 bv = *(const float4*)&Bs[k * 64 + tx * 4];
                        float am[4] = {av.x, av.y, av.z, av.w};
                        float bb[4] = {bv.x, bv.y, bv.z, bv.w};
#pragma unroll
                        for (int i = 0; i < 4; i++)
#pragma unroll
                            for (int j = 0; j < 4; j++) acc[i][j] += am[i] * bb[j];
                    }
                    asm volatile("bar.sync %0, 256;" :: "r"(barid) : "memory");
                }
#pragma unroll
                for (int i = 0; i < 4; i++)
#pragma unroll
                    for (int j = 0; j < 4; j++) {
                        int n = n0 + tx * 4 + j;
                        g_X[(size_t)(row0 + ty * 4 + i) * DD + n] = acc[i][j] + bi[n];
                    }
            }
        }
        __syncthreads();
    }

    // =============== prologue 2: warp-parallel LN of the same 256 rows ===============
    {
        const float4 g0 = *(const float4*)(lng + lane * 16);
        const float4 g1 = *(const float4*)(lng + lane * 16 + 4);
        const float4 g2 = *(const float4*)(lng + lane * 16 + 8);
        const float4 g3 = *(const float4*)(lng + lane * 16 + 12);
        const float4 h0 = *(const float4*)(lnb + lane * 16);
        const float4 h1 = *(const float4*)(lnb + lane * 16 + 4);
        const float4 h2 = *(const float4*)(lnb + lane * 16 + 8);
        const float4 h3 = *(const float4*)(lnb + lane * 16 + 12);

        for (int r = 0; r < 16; r++) {
            const int row = b * 256 + warp * 16 + r;
            float* xp = g_X + (size_t)row * DD + lane * 16;
            float4 v0 = *(float4*)(xp);
            float4 v1 = *(float4*)(xp + 4);
            float4 v2 = *(float4*)(xp + 8);
            float4 v3 = *(float4*)(xp + 12);

            float s = v0.x + v0.y + v0.z + v0.w + v1.x + v1.y + v1.z + v1.w
                    + v2.x + v2.y + v2.z + v2.w + v3.x + v3.y + v3.z + v3.w;
#pragma unroll
            for (int o = 16; o; o >>= 1) s += __shfl_xor_sync(0xffffffffu, s, o);
            float mean = s * (1.f / DD);

            float q =
                (v0.x-mean)*(v0.x-mean) + (v0.y-mean)*(v0.y-mean) +
                (v0.z-mean)*(v0.z-mean) + (v0.w-mean)*(v0.w-mean) +
                (v1.x-mean)*(v1.x-mean) + (v1.y-mean)*(v1.y-mean) +
                (v1.z-mean)*(v1.z-mean) + (v1.w-mean)*(v1.w-mean) +
                (v2.x-mean)*(v2.x-mean) + (v2.y-mean)*(v2.y-mean) +
                (v2.z-mean)*(v2.z-mean) + (v2.w-mean)*(v2.w-mean) +
                (v3.x-mean)*(v3.x-mean) + (v3.y-mean)*(v3.y-mean) +
                (v3.z-mean)*(v3.z-mean) + (v3.w-mean)*(v3.w-mean);
#pragma unroll
            for (int o = 16; o; o >>= 1) q += __shfl_xor_sync(0xffffffffu, q, o);
            float rs = rsqrtf(q * (1.f / DD) + 1e-5f);

            float mval = mask[row];
            v0.x = ((v0.x-mean)*rs*g0.x + h0.x)*mval; v0.y = ((v0.y-mean)*rs*g0.y + h0.y)*mval;
            v0.z = ((v0.z-mean)*rs*g0.z + h0.z)*mval; v0.w = ((v0.w-mean)*rs*g0.w + h0.w)*mval;
            v1.x = ((v1.x-mean)*rs*g1.x + h1.x)*mval; v1.y = ((v1.y-mean)*rs*g1.y + h1.y)*mval;
            v1.z = ((v1.z-mean)*rs*g1.z + h1.z)*mval; v1.w = ((v1.w-mean)*rs*g1.w + h1.w)*mval;
            v2.x = ((v2.x-mean)*rs*g2.x + h2.x)*mval; v2.y = ((v2.y-mean)*rs*g2.y + h2.y)*mval;
            v2.z = ((v2.z-mean)*rs*g2.z + h2.z)*mval; v2.w = ((v2.w-mean)*rs*g2.w + h2.w)*mval;
            v3.x = ((v3.x-mean)*rs*g3.x + h3.x)*mval; v3.y = ((v3.y-mean)*rs*g3.y + h3.y)*mval;
            v3.z = ((v3.z-mean)*rs*g3.z + h3.z)*mval; v3.w = ((v3.w-mean)*rs*g3.w + h3.w)*mval;
            *(float4*)(xp)      = v0;
            *(float4*)(xp + 4)  = v1;
            *(float4*)(xp + 8)  = v2;
            *(float4*)(xp + 12) = v3;
        }
    }

    // init carry (registers for block b)
    float hr = 0.f, gsr = 0.f;
    float lngv = 0.f, lnbv = 0.f;
    if (b < NN) {
        float s = START[tid];
        g_ht[b * DD + tid] = s;
        hr = s; gsr = s;
        lngv = lng[tid]; lnbv = lnb[tid];
    }
    gbar(&barc);

    // =============== scan ===============
    const int mg = lane & 15;
    const int ng = lane >> 4;
    const int k0 = warp * 64;                 // 16-way k-split
    float* const Abuf = (float*)smch + warp * PWS;
    const float b1v = b1[nA0 + (tid & 7)];
    const float b2v0 = b2[nB0 + (tid & 15)];
    const float b2v1 = b2[nB0 + ((tid + 512) & 15)];
    const int mr0 = 2 * mg, mr1 = 2 * mg + 1, mr2 = 2 * mg + 32, mr3 = 2 * mg + 33;

    for (int t = 0; t < SS; t++) {
        // ---------- phase A: inter = gelu(cat @ W1 + b1); block owns 8 cols ----------
        {
            ull acc[4][2];
#pragma unroll
            for (int i = 0; i < 4; i++) { acc[i][0] = 0; acc[i][1] = 0; }

            const float *base0, *base1;
            if (warp < 8) {
                base0 = g_ht + (size_t)lane * DD + k0;
                base1 = g_ht + (size_t)(lane + 32) * DD + k0;
            } else {
                size_t off = (size_t)t * DD + (k0 - 512);
                base0 = g_X + (size_t)lane * SS * DD + off;
                base1 = g_X + (size_t)(lane + 32) * SS * DD + off;
            }
            float4 c0 = ldcg4(base0), c1 = ldcg4(base0 + 4);
            float4 c2 = ldcg4(base1), c3 = ldcg4(base1 + 4);

            for (int kc = 0; kc < 8; kc++) {
                float* sb = Abuf + ((kc & 1) << 9);
                sb[0*64+lane] = c0.x; sb[1*64+lane] = c0.y;
                sb[2*64+lane] = c0.z; sb[3*64+lane] = c0.w;
                sb[4*64+lane] = c1.x; sb[5*64+lane] = c1.y;
                sb[6*64+lane] = c1.z; sb[7*64+lane] = c1.w;
                sb[0*64+lane+32] = c2.x; sb[1*64+lane+32] = c2.y;
                sb[2*64+lane+32] = c2.z; sb[3*64+lane+32] = c2.w;
                sb[4*64+lane+32] = c3.x; sb[5*64+lane+32] = c3.y;
                sb[6*64+lane+32] = c3.z; sb[7*64+lane+32] = c3.w;
                if (kc < 7) {
                    const float* q0 = base0 + (kc + 1) * 8;
                    const float* q1 = base1 + (kc + 1) * 8;
                    c0 = ldcg4(q0); c1 = ldcg4(q0 + 4);
                    c2 = ldcg4(q1); c3 = ldcg4(q1 + 4);
                }
                __syncwarp();
                const float* wk = sW1 + (size_t)(k0 + kc * 8) * 8 + ng * 4;
#pragma unroll
                for (int kk = 0; kk < 8; kk++) {
                    float2 alo = *(const float2*)(sb + kk * 64 + 2 * mg);
                    float2 ahi = *(const float2*)(sb + kk * 64 + 32 + 2 * mg);
                    ull a0 = dup2(alo.x), a1 = dup2(alo.y);
                    ull a2 = dup2(ahi.x), a3 = dup2(ahi.y);
                    ulonglong2 w = *(const ulonglong2*)(wk + kk * 8);
                    fma2(acc[0][0], a0, w.x); fma2(acc[0][1], a0, w.y);
                    fma2(acc[1][0], a1, w.x); fma2(acc[1][1], a1, w.y);
                    fma2(acc[2][0], a2, w.x); fma2(acc[2][1], a2, w.y);
                    fma2(acc[3][0], a3, w.x); fma2(acc[3][1], a3, w.y);
                }
            }
            __syncwarp();
            // partials: [n][68] layout, n = ng*4 + 2p (+1)
            {
                const int mr[4] = {mr0, mr1, mr2, mr3};
#pragma unroll
                for (int mi = 0; mi < 4; mi++)
#pragma unroll
                    for (int p = 0; p < 2; p++) {
                        float2 f = unp(acc[mi][p]);
                        int n = ng * 4 + 2 * p;
                        Abuf[n * 68 + mr[mi]] = f.x;
                        Abuf[(n + 1) * 68 + mr[mi]] = f.y;
                    }
            }
            __syncthreads();
            {
                int nl = tid & 7, m = tid >> 3;
                float s = b1v;
#pragma unroll
                for (int w = 0; w < 16; w++) s += Rall[w * PWS + nl * 68 + m];
                __stcg(&g_inter[m * CC + nA0 + nl], gelu_t(s));
            }
        }
        gbar(&barc);

        // ---------- phase B: cont = inter @ W2 + b2 (M-pair f32x2, dup'd weights) ----------
        {
            ull acc[2][8];
#pragma unroll
            for (int p = 0; p < 2; p++)
#pragma unroll
                for (int j = 0; j < 8; j++) acc[p][j] = 0;

            const float* base0 = g_inter + (size_t)lane * CC + k0;
            const float* base1 = g_inter + (size_t)(lane + 32) * CC + k0;
            float4 c0 = ldcg4(base0), c1 = ldcg4(base0 + 4);
            float4 c2 = ldcg4(base1), c3 = ldcg4(base1 + 4);

            for (int kc = 0; kc < 8; kc++) {
                float* sb = Abuf + ((kc & 1) << 9);
                sb[0*64+lane] = c0.x; sb[1*64+lane] = c0.y;
                sb[2*64+lane] = c0.z; sb[3*64+lane] = c0.w;
                sb[4*64+lane] = c1.x; sb[5*64+lane] = c1.y;
                sb[6*64+lane] = c1.z; sb[7*64+lane] = c1.w;
                sb[0*64+lane+32] = c2.x; sb[1*64+lane+32] = c2.y;
                sb[2*64+lane+32] = c2.z; sb[3*64+lane+32] = c2.w;
                sb[4*64+lane+32] = c3.x; sb[5*64+lane+32] = c3.y;
                sb[6*64+lane+32] = c3.z; sb[7*64+lane+32] = c3.w;
                if (kc < 7) {
                    const float* q0 = base0 + (kc + 1) * 8;
                    const float* q1 = base1 + (kc + 1) * 8;
                    c0 = ldcg4(q0); c1 = ldcg4(q0 + 4);
                    c2 = ldcg4(q1); c3 = ldcg4(q1 + 4);
                }
                __syncwarp();
                const ull* wd = sW2d + (size_t)(k0 + kc * 8) * 16 + ng * 8;
#pragma unroll
                for (int kk = 0; kk < 8; kk++) {
                    // A: 4 consecutive m rows = 2 f32x2 M-pairs, one LDS.128
                    ulonglong2 ap = *(const ulonglong2*)(sb + kk * 64 + 4 * mg);
                    const ull* wr = wd + (size_t)kk * 16;
                    ulonglong2 w01 = *(const ulonglong2*)(wr);
                    ulonglong2 w23 = *(const ulonglong2*)(wr + 2);
                    ulonglong2 w45 = *(const ulonglong2*)(wr + 4);
                    ulonglong2 w67 = *(const ulonglong2*)(wr + 6);
                    fma2(acc[0][0], ap.x, w01.x); fma2(acc[1][0], ap.y, w01.x);
                    fma2(acc[0][1], ap.x, w01.y); fma2(acc[1][1], ap.y, w01.y);
                    fma2(acc[0][2], ap.x, w23.x); fma2(acc[1][2], ap.y, w23.x);
                    fma2(acc[0][3], ap.x, w23.y); fma2(acc[1][3], ap.y, w23.y);
                    fma2(acc[0][4], ap.x, w45.x); fma2(acc[1][4], ap.y, w45.x);
                    fma2(acc[0][5], ap.x, w45.y); fma2(acc[1][5], ap.y, w45.y);
                    fma2(acc[0][6], ap.x, w67.x); fma2(acc[1][6], ap.y, w67.x);
                    fma2(acc[0][7], ap.x, w67.y); fma2(acc[1][7], ap.y, w67.y);
                }
            }
            __syncwarp();
            // partials: [n][66] layout; acc[p][j] = (C[4mg+2p][n], C[4mg+2p+1][n])
#pragma unroll
            for (int p = 0; p < 2; p++)
#pragma unroll
                for (int j = 0; j < 8; j++) {
                    int n = 8 * ng + j;
                    *(ull*)(Abuf + n * 66 + 4 * mg + 2 * p) = acc[p][j];
                }
            __syncthreads();
#pragma unroll
            for (int j = 0; j < 2; j++) {
                int idx = tid + 512 * j;
                int nl = idx & 15, m = idx >> 4;
                float s = (j == 0) ? b2v0 : b2v1;
#pragma unroll
                for (int w = 0; w < 16; w++) s += Rall[w * PWS + nl * 66 + m];
                __stcg(&g_cont[m * (4 * DD) + nB0 + nl], s);
            }
        }
        gbar(&barc);

        // ---------- phase C: gates + LN + state update (blocks 0..63) ----------
        if (b < NN) {
            float mval = mask[(size_t)b * SS + t];
            const float* cb = g_cont + b * (4 * DD);
            float c0 = __ldcg(cb + tid);
            float c1 = __ldcg(cb + 512 + tid);
            float c2 = __ldcg(cb + 1024 + tid);
            float c3 = __ldcg(cb + 1536 + tid);
            float x0 = g_X[((size_t)b * SS + t) * DD + tid];
            float v = sigm(c0) * hr + sigm(c1) * x0 + sigm(c2) * c3;
            float mean = bsum512(v, scC) * (1.f / DD);
            float e = v - mean;
            float var = bsum512(e * e, scC) * (1.f / DD);
            float rs = rsqrtf(var + 1e-5f);
            float hn = e * rs * lngv + lnbv;
            hr = hn;
            g_ht[b * DD + tid] = hn;
            out[((size_t)b * SS + t) * DD + tid] = hn * mval;
            gsr = mval * hn + (1.f - mval) * gsr;
        }
        gbar(&barc);
    }

    // final global_state
    if (b < NN) {
        out[(size_t)NN * SS * DD + b * DD + tid] = gsr;
    }
}

extern "C" void kernel_launch(void* const* d_in, const int* in_sizes, int n_in,
                              void* d_out, int out_size) {
    (void)in_sizes; (void)n_in; (void)out_size;
    const float* seq   = (const float*)d_in[0];
    const float* mask  = (const float*)d_in[1];
    const float* START = (const float*)d_in[2];
    const float* Wi    = (const float*)d_in[3];
    const float* bi    = (const float*)d_in[4];
    const float* W1    = (const float*)d_in[5];
    const float* b1    = (const float*)d_in[6];
    const float* W2    = (const float*)d_in[7];
    const float* b2    = (const float*)d_in[8];
    const float* lng   = (const float*)d_in[9];
    const float* lnb   = (const float*)d_in[10];
    float* out = (float*)d_out;

    static bool attr_done = false;
    if (!attr_done) {
        cudaFuncSetAttribute(k_main, cudaFuncAttributeMaxDynamicSharedMemorySize,
                             SMEM_MAIN);
        attr_done = true;
    }

    k_reset<<<1, 64>>>();
    k_main<<<GRID, NTHREADS, SMEM_MAIN>>>(seq, mask, START, Wi, bi,
                                          W1, b1, W2, b2, lng, lnb, out);
}

// round 17
// speedup vs baseline: 1.2564x; 1.2564x over previous
#include <cuda_runtime.h>

#define NN 64
#define SS 512
#define DD 512
#define CC 1024
#define GRID 128
#define NTHREADS 512

// dynamic smem layout for k_main (bytes):
//   [0,      67584)   per-warp region: 16 warps x 1056 floats (staging + partials)
//                       (prologue: 2 teams x 2048 floats of GEMM tiles)
//   [67584,  83968)   sW1: 512 rows x 8 floats   (W1[0:512] slice — ht part only)
//   [83968, 149504)   sW2: 1024 rows x 16 floats (block's W2 slice)
#define PWS 1056
#define SMEM_MAIN (16 * PWS * 4 + 16384 + 65536)

// ---------------- device scratch (static, no allocations) ----------------
__device__ float g_X[(size_t)NN * SS * DD];       // LN'd masked inputs (64 MB)
__device__ float g_interx[(size_t)NN * SS * CC];  // X @ W1[512:] precompute (128 MB)
__device__ float g_ht[NN * DD];
__device__ float g_inter[NN * CC];
__device__ float g_cont[NN * 4 * DD];
__device__ unsigned g_gcnt[8 * 64];               // 8 group counters, 256B apart
__device__ unsigned g_rcnt;
__device__ unsigned g_sense;

typedef unsigned long long ull;

__device__ __forceinline__ void fma2(ull& d, ull a, ull b) {
    asm("fma.rn.f32x2 %0, %1, %2, %0;" : "+l"(d) : "l"(a), "l"(b));
}
__device__ __forceinline__ ull dup2(float f) {
    ull r; asm("mov.b64 %0, {%1, %1};" : "=l"(r) : "f"(f)); return r;
}
__device__ __forceinline__ float2 unp(ull v) {
    float2 r; asm("mov.b64 {%0, %1}, %2;" : "=f"(r.x), "=f"(r.y) : "l"(v)); return r;
}
__device__ __forceinline__ float sigm(float x) { return 1.f / (1.f + expf(-x)); }
__device__ __forceinline__ float gelu_t(float x) {
    float u = x + 0.044715f * x * x * x;
    return 0.5f * x * (1.f + tanhf(0.7978845608028654f * u));
}
__device__ __forceinline__ float4 ldcg4(const float* p) {
    return __ldcg((const float4*)p);
}

// barrier-state reset before each k_main launch (graph-replay safe)
__global__ void k_reset() {
    for (int i = threadIdx.x; i < 8 * 64; i += 64) g_gcnt[i] = 0;
    if (threadIdx.x == 0) { g_rcnt = 0; g_sense = 0; }
}

// Two-level fence-free global barrier: 16-way group arrive + 8-way root.
__device__ __forceinline__ void gbar(unsigned* barc) {
    __syncthreads();
    unsigned target = ++(*barc);
    if (threadIdx.x == 0) {
        unsigned* gc = &g_gcnt[(blockIdx.x >> 4) * 64];
        unsigned prev;
        asm volatile("atom.acq_rel.gpu.add.u32 %0, [%1], 1;"
                     : "=r"(prev) : "l"(gc) : "memory");
        if (prev == 15) {
            unsigned pr;
            asm volatile("atom.acq_rel.gpu.add.u32 %0, [%1], 1;"
                         : "=r"(pr) : "l"(&g_rcnt) : "memory");
            if (pr == 7) {
#pragma unroll
                for (int g = 0; g < 8; g++)
                    asm volatile("st.relaxed.gpu.u32 [%0], %1;"
                                 :: "l"(&g_gcnt[g * 64]), "r"(0u) : "memory");
                asm volatile("st.relaxed.gpu.u32 [%0], %1;"
                             :: "l"(&g_rcnt), "r"(0u) : "memory");
                asm volatile("st.release.gpu.u32 [%0], %1;"
                             :: "l"(&g_sense), "r"(target) : "memory");
            }
        }
        unsigned s;
        do {
            asm volatile("ld.relaxed.gpu.u32 %0, [%1];"
                         : "=r"(s) : "l"(&g_sense) : "memory");
        } while (s < target);
        asm volatile("ld.acquire.gpu.u32 %0, [%1];"
                     : "=r"(s) : "l"(&g_sense) : "memory");
    }
    __syncthreads();
}

// block sum over 512 threads (16 warps)
__device__ __forceinline__ float bsum512(float v, float* sc) {
    int lane = threadIdx.x & 31, w = threadIdx.x >> 5;
#pragma unroll
    for (int o = 16; o; o >>= 1) v += __shfl_xor_sync(0xffffffffu, v, o);
    if (lane == 0) sc[w] = v;
    __syncthreads();
    if (w == 0) {
        float s = (lane < 16) ? sc[lane] : 0.f;
#pragma unroll
        for (int o = 8; o; o >>= 1) s += __shfl_xor_sync(0xffffffffu, s, o);
        if (lane == 0) sc[16] = s;
    }
    __syncthreads();
    float r = sc[16];
    __syncthreads();
    return r;
}

__global__ void __launch_bounds__(NTHREADS, 1) k_main(
    const float* __restrict__ seq, const float* __restrict__ mask,
    const float* __restrict__ START,
    const float* __restrict__ Wi, const float* __restrict__ bi,
    const float* __restrict__ W1, const float* __restrict__ b1,
    const float* __restrict__ W2, const float* __restrict__ b2,
    const float* __restrict__ lng, const float* __restrict__ lnb,
    float* __restrict__ out)
{
    extern __shared__ char smch[];
    float* const Rall = (float*)smch;                      // 16 x PWS floats
    float* const sW1 = (float*)(smch + 16 * PWS * 4);      // [512][8]
    float* const sW2 = (float*)(smch + 16 * PWS * 4 + 16384);  // [1024][16]
    __shared__ float scC[32];

    const int tid = threadIdx.x;
    const int lane = tid & 31;
    const int warp = tid >> 5;
    const int b = blockIdx.x;
    unsigned barc = 0;

    const int nA0 = b * 8;
    const int nB0 = b * 16;

    // ---- one-time: weight slices into smem ----
    for (int i = tid; i < 512 * 2; i += NTHREADS) {     // sW1: 1024 float4 (rows 0..511)
        int row = i >> 1, half = i & 1;
        *(float4*)(sW1 + (size_t)row * 8 + half * 4) =
            *(const float4*)(W1 + (size_t)row * CC + nA0 + half * 4);
    }
    for (int i = tid; i < CC * 4; i += NTHREADS) {      // sW2: 4096 float4
        int row = i >> 2, q = i & 3;
        *(float4*)(sW2 + (size_t)row * 16 + q * 4) =
            *(const float4*)(W2 + (size_t)row * (4 * DD) + nB0 + q * 4);
    }

    const int team = warp >> 3;
    const int ttid = tid & 255;
    const int barid = team + 1;

    // =============== prologue 1: g_X stripe = (seq*mask) @ Wi + bi ===============
    {
        float* const As = (float*)smch + team * 2048;
        float* const Bs = As + 1024;
        const int lm = ttid >> 2, kq = (ttid & 3) * 4;
        const int bk = ttid >> 4, bn = (ttid & 15) * 4;
        const int ty = ttid >> 4, tx = ttid & 15;

        for (int rt = 0; rt < 2; rt++) {
            const int row0 = b * 256 + (team * 2 + rt) * 64;
            const float mval = mask[row0 + lm];
            for (int ct = 0; ct < 8; ct++) {
                const int n0 = ct * 64;
                float acc[4][4];
#pragma unroll
                for (int i = 0; i < 4; i++)
#pragma unroll
                    for (int j = 0; j < 4; j++) acc[i][j] = 0.f;

                for (int kt = 0; kt < DD / 16; kt++) {
                    float4 a = *(const float4*)&seq[(size_t)(row0 + lm) * DD + kt * 16 + kq];
                    As[(kq + 0) * 64 + lm] = a.x * mval;
                    As[(kq + 1) * 64 + lm] = a.y * mval;
                    As[(kq + 2) * 64 + lm] = a.z * mval;
                    As[(kq + 3) * 64 + lm] = a.w * mval;
                    *(float4*)&Bs[bk * 64 + bn] =
                        *(const float4*)&Wi[(size_t)(kt * 16 + bk) * DD + n0 + bn];
                    asm volatile("bar.sync %0, 256;" :: "r"(barid) : "memory");
#pragma unroll
                    for (int k = 0; k < 16; k++) {
                        float4 av = *(const float4*)&As[k * 64 + ty * 4];
                        float4 bv = *(const float4*)&Bs[k * 64 + tx * 4];
                        float am[4] = {av.x, av.y, av.z, av.w};
                        float bb[4] = {bv.x, bv.y, bv.z, bv.w};
#pragma unroll
                        for (int i = 0; i < 4; i++)
#pragma unroll
                            for (int j = 0; j < 4; j++) acc[i][j] += am[i] * bb[j];
                    }
                    asm volatile("bar.sync %0, 256;" :: "r"(barid) : "memory");
                }
#pragma unroll
                for (int i = 0; i < 4; i++)
#pragma unroll
                    for (int j = 0; j < 4; j++) {
                        int n = n0 + tx * 4 + j;
                        g_X[(size_t)(row0 + ty * 4 + i) * DD + n] = acc[i][j] + bi[n];
                    }
            }
        }
        __syncthreads();
    }

    // =============== prologue 2: warp-parallel LN of the same 256 rows ===============
    {
        const float4 g0 = *(const float4*)(lng + lane * 16);
        const float4 g1 = *(const float4*)(lng + lane * 16 + 4);
        const float4 g2 = *(const float4*)(lng + lane * 16 + 8);
        const float4 g3 = *(const float4*)(lng + lane * 16 + 12);
        const float4 h0 = *(const float4*)(lnb + lane * 16);
        const float4 h1 = *(const float4*)(lnb + lane * 16 + 4);
        const float4 h2 = *(const float4*)(lnb + lane * 16 + 8);
        const float4 h3 = *(const float4*)(lnb + lane * 16 + 12);

        for (int r = 0; r < 16; r++) {
            const int row = b * 256 + warp * 16 + r;
            float* xp = g_X + (size_t)row * DD + lane * 16;
            float4 v0 = *(float4*)(xp);
            float4 v1 = *(float4*)(xp + 4);
            float4 v2 = *(float4*)(xp + 8);
            float4 v3 = *(float4*)(xp + 12);

            float s = v0.x + v0.y + v0.z + v0.w + v1.x + v1.y + v1.z + v1.w
                    + v2.x + v2.y + v2.z + v2.w + v3.x + v3.y + v3.z + v3.w;
#pragma unroll
            for (int o = 16; o; o >>= 1) s += __shfl_xor_sync(0xffffffffu, s, o);
            float mean = s * (1.f / DD);

            float q =
                (v0.x-mean)*(v0.x-mean) + (v0.y-mean)*(v0.y-mean) +
                (v0.z-mean)*(v0.z-mean) + (v0.w-mean)*(v0.w-mean) +
                (v1.x-mean)*(v1.x-mean) + (v1.y-mean)*(v1.y-mean) +
                (v1.z-mean)*(v1.z-mean) + (v1.w-mean)*(v1.w-mean) +
                (v2.x-mean)*(v2.x-mean) + (v2.y-mean)*(v2.y-mean) +
                (v2.z-mean)*(v2.z-mean) + (v2.w-mean)*(v2.w-mean) +
                (v3.x-mean)*(v3.x-mean) + (v3.y-mean)*(v3.y-mean) +
                (v3.z-mean)*(v3.z-mean) + (v3.w-mean)*(v3.w-mean);
#pragma unroll
            for (int o = 16; o; o >>= 1) q += __shfl_xor_sync(0xffffffffu, q, o);
            float rs = rsqrtf(q * (1.f / DD) + 1e-5f);

            float mval = mask[row];
            v0.x = ((v0.x-mean)*rs*g0.x + h0.x)*mval; v0.y = ((v0.y-mean)*rs*g0.y + h0.y)*mval;
            v0.z = ((v0.z-mean)*rs*g0.z + h0.z)*mval; v0.w = ((v0.w-mean)*rs*g0.w + h0.w)*mval;
            v1.x = ((v1.x-mean)*rs*g1.x + h1.x)*mval; v1.y = ((v1.y-mean)*rs*g1.y + h1.y)*mval;
            v1.z = ((v1.z-mean)*rs*g1.z + h1.z)*mval; v1.w = ((v1.w-mean)*rs*g1.w + h1.w)*mval;
            v2.x = ((v2.x-mean)*rs*g2.x + h2.x)*mval; v2.y = ((v2.y-mean)*rs*g2.y + h2.y)*mval;
            v2.z = ((v2.z-mean)*rs*g2.z + h2.z)*mval; v2.w = ((v2.w-mean)*rs*g2.w + h2.w)*mval;
            v3.x = ((v3.x-mean)*rs*g3.x + h3.x)*mval; v3.y = ((v3.y-mean)*rs*g3.y + h3.y)*mval;
            v3.z = ((v3.z-mean)*rs*g3.z + h3.z)*mval; v3.w = ((v3.w-mean)*rs*g3.w + h3.w)*mval;
            *(float4*)(xp)      = v0;
            *(float4*)(xp + 4)  = v1;
            *(float4*)(xp + 8)  = v2;
            *(float4*)(xp + 12) = v3;
        }
        __syncthreads();
    }

    // =============== prologue 3: interx stripe = g_X stripe @ W1[512:] ===============
    // block-local rows (written by this block above), 4 row-tiles x 16 col-tiles
    {
        float* const As = (float*)smch + team * 2048;
        float* const Bs = As + 1024;
        const int lm = ttid >> 2, kq = (ttid & 3) * 4;
        const int bk = ttid >> 4, bn = (ttid & 15) * 4;
        const int ty = ttid >> 4, tx = ttid & 15;

        for (int rt = 0; rt < 2; rt++) {
            const int row0 = b * 256 + (team * 2 + rt) * 64;
            for (int ct = 0; ct < 16; ct++) {
                const int n0 = ct * 64;
                float acc[4][4];
#pragma unroll
                for (int i = 0; i < 4; i++)
#pragma unroll
                    for (int j = 0; j < 4; j++) acc[i][j] = 0.f;

                for (int kt = 0; kt < DD / 16; kt++) {
                    float4 a = *(const float4*)&g_X[(size_t)(row0 + lm) * DD + kt * 16 + kq];
                    As[(kq + 0) * 64 + lm] = a.x;
                    As[(kq + 1) * 64 + lm] = a.y;
                    As[(kq + 2) * 64 + lm] = a.z;
                    As[(kq + 3) * 64 + lm] = a.w;
                    *(float4*)&Bs[bk * 64 + bn] =
                        *(const float4*)&W1[(size_t)(512 + kt * 16 + bk) * CC + n0 + bn];
                    asm volatile("bar.sync %0, 256;" :: "r"(barid) : "memory");
#pragma unroll
                    for (int k = 0; k < 16; k++) {
                        float4 av = *(const float4*)&As[k * 64 + ty * 4];
                        float4 bv = *(const float4*)&Bs[k * 64 + tx * 4];
                        float am[4] = {av.x, av.y, av.z, av.w};
                        float bb[4] = {bv.x, bv.y, bv.z, bv.w};
#pragma unroll
                        for (int i = 0; i < 4; i++)
#pragma unroll
                            for (int j = 0; j < 4; j++) acc[i][j] += am[i] * bb[j];
                    }
                    asm volatile("bar.sync %0, 256;" :: "r"(barid) : "memory");
                }
#pragma unroll
                for (int i = 0; i < 4; i++)
#pragma unroll
                    for (int j = 0; j < 4; j++) {
                        g_interx[(size_t)(row0 + ty * 4 + i) * CC + n0 + tx * 4 + j] = acc[i][j];
                    }
            }
        }
        __syncthreads();
    }

    // init carry (registers for block b)
    float hr = 0.f, gsr = 0.f;
    float lngv = 0.f, lnbv = 0.f;
    if (b < NN) {
        float s = START[tid];
        g_ht[b * DD + tid] = s;
        hr = s; gsr = s;
        lngv = lng[tid]; lnbv = lnb[tid];
    }
    gbar(&barc);

    // =============== scan ===============
    const int mg = lane & 15;
    const int ng = lane >> 4;
    const int k0a = warp * 32;                // phase A: 16-way split of K=512
    const int k0b = warp * 64;                // phase B: 16-way split of K=1024
    float* const Abuf = (float*)smch + warp * PWS;
    const float b1v = b1[nA0 + (tid & 7)];
    const float b2v0 = b2[nB0 + (tid & 15)];
    const float b2v1 = b2[nB0 + ((tid + 512) & 15)];
    const int mr0 = 2 * mg, mr1 = 2 * mg + 1, mr2 = 2 * mg + 32, mr3 = 2 * mg + 33;
    const size_t ix_off = ((size_t)(tid >> 3) * SS) * CC + nA0 + (tid & 7);

    for (int t = 0; t < SS; t++) {
        // ---------- phase A: inter = gelu(ht @ W1[0:512] + interx[t] + b1) ----------
        {
            float xa = __ldcg(&g_interx[ix_off + (size_t)t * CC]);

            ull acc[4][2];
#pragma unroll
            for (int i = 0; i < 4; i++) { acc[i][0] = 0; acc[i][1] = 0; }

            const float* base0 = g_ht + (size_t)lane * DD + k0a;
            const float* base1 = g_ht + (size_t)(lane + 32) * DD + k0a;
            float4 c0 = ldcg4(base0), c1 = ldcg4(base0 + 4);
            float4 c2 = ldcg4(base1), c3 = ldcg4(base1 + 4);

            for (int kc = 0; kc < 4; kc++) {
                float* sb = Abuf + ((kc & 1) << 9);
                sb[0*64+lane] = c0.x; sb[1*64+lane] = c0.y;
                sb[2*64+lane] = c0.z; sb[3*64+lane] = c0.w;
                sb[4*64+lane] = c1.x; sb[5*64+lane] = c1.y;
                sb[6*64+lane] = c1.z; sb[7*64+lane] = c1.w;
                sb[0*64+lane+32] = c2.x; sb[1*64+lane+32] = c2.y;
                sb[2*64+lane+32] = c2.z; sb[3*64+lane+32] = c2.w;
                sb[4*64+lane+32] = c3.x; sb[5*64+lane+32] = c3.y;
                sb[6*64+lane+32] = c3.z; sb[7*64+lane+32] = c3.w;
                if (kc < 3) {
                    const float* q0 = base0 + (kc + 1) * 8;
                    const float* q1 = base1 + (kc + 1) * 8;
                    c0 = ldcg4(q0); c1 = ldcg4(q0 + 4);
                    c2 = ldcg4(q1); c3 = ldcg4(q1 + 4);
                }
                __syncwarp();
                const float* wk = sW1 + (size_t)(k0a + kc * 8) * 8 + ng * 4;
#pragma unroll
                for (int kk = 0; kk < 8; kk++) {
                    float2 alo = *(const float2*)(sb + kk * 64 + 2 * mg);
                    float2 ahi = *(const float2*)(sb + kk * 64 + 32 + 2 * mg);
                    ull a0 = dup2(alo.x), a1 = dup2(alo.y);
                    ull a2 = dup2(ahi.x), a3 = dup2(ahi.y);
                    ulonglong2 w = *(const ulonglong2*)(wk + kk * 8);
                    fma2(acc[0][0], a0, w.x); fma2(acc[0][1], a0, w.y);
                    fma2(acc[1][0], a1, w.x); fma2(acc[1][1], a1, w.y);
                    fma2(acc[2][0], a2, w.x); fma2(acc[2][1], a2, w.y);
                    fma2(acc[3][0], a3, w.x); fma2(acc[3][1], a3, w.y);
                }
            }
            __syncwarp();
            {
                const int mr[4] = {mr0, mr1, mr2, mr3};
#pragma unroll
                for (int mi = 0; mi < 4; mi++)
#pragma unroll
                    for (int p = 0; p < 2; p++) {
                        float2 f = unp(acc[mi][p]);
                        int n = ng * 4 + 2 * p;
                        Abuf[n * 66 + mr[mi]] = f.x;
                        Abuf[(n + 1) * 66 + mr[mi]] = f.y;
                    }
            }
            __syncthreads();
            {
                int nl = tid & 7, m = tid >> 3;
                float s = b1v + xa;
#pragma unroll
                for (int w = 0; w < 16; w++) s += Rall[w * PWS + nl * 66 + m];
                __stcg(&g_inter[m * CC + nA0 + nl], gelu_t(s));
            }
        }
        gbar(&barc);

        // ---------- phase B: cont = inter @ W2 + b2; block owns 16 cols ----------
        {
            ull acc[4][4];
#pragma unroll
            for (int i = 0; i < 4; i++)
#pragma unroll
                for (int j = 0; j < 4; j++) acc[i][j] = 0;

            const float* base0 = g_inter + (size_t)lane * CC + k0b;
            const float* base1 = g_inter + (size_t)(lane + 32) * CC + k0b;
            float4 c0 = ldcg4(base0), c1 = ldcg4(base0 + 4);
            float4 c2 = ldcg4(base1), c3 = ldcg4(base1 + 4);

            for (int kc = 0; kc < 8; kc++) {
                float* sb = Abuf + ((kc & 1) << 9);
                sb[0*64+lane] = c0.x; sb[1*64+lane] = c0.y;
                sb[2*64+lane] = c0.z; sb[3*64+lane] = c0.w;
                sb[4*64+lane] = c1.x; sb[5*64+lane] = c1.y;
                sb[6*64+lane] = c1.z; sb[7*64+lane] = c1.w;
                sb[0*64+lane+32] = c2.x; sb[1*64+lane+32] = c2.y;
                sb[2*64+lane+32] = c2.z; sb[3*64+lane+32] = c2.w;
                sb[4*64+lane+32] = c3.x; sb[5*64+lane+32] = c3.y;
                sb[6*64+lane+32] = c3.z; sb[7*64+lane+32] = c3.w;
                if (kc < 7) {
                    const float* q0 = base0 + (kc + 1) * 8;
                    const float* q1 = base1 + (kc + 1) * 8;
                    c0 = ldcg4(q0); c1 = ldcg4(q0 + 4);
                    c2 = ldcg4(q1); c3 = ldcg4(q1 + 4);
                }
                __syncwarp();
                const float* wk = sW2 + (size_t)(k0b + kc * 8) * 16 + ng * 8;
#pragma unroll
                for (int kk = 0; kk < 8; kk++) {
                    float2 alo = *(const float2*)(sb + kk * 64 + 2 * mg);
                    float2 ahi = *(const float2*)(sb + kk * 64 + 32 + 2 * mg);
                    ull a0 = dup2(alo.x), a1 = dup2(alo.y);
                    ull a2 = dup2(ahi.x), a3 = dup2(ahi.y);
                    const float* wr = wk + kk * 16;
                    ulonglong2 w0 = *(const ulonglong2*)(wr);
                    ulonglong2 w1 = *(const ulonglong2*)(wr + 4);
                    fma2(acc[0][0], a0, w0.x); fma2(acc[0][1], a0, w0.y);
                    fma2(acc[0][2], a0, w1.x); fma2(acc[0][3], a0, w1.y);
                    fma2(acc[1][0], a1, w0.x); fma2(acc[1][1], a1, w0.y);
                    fma2(acc[1][2], a1, w1.x); fma2(acc[1][3], a1, w1.y);
                    fma2(acc[2][0], a2, w0.x); fma2(acc[2][1], a2, w0.y);
                    fma2(acc[2][2], a2, w1.x); fma2(acc[2][3], a2, w1.y);
                    fma2(acc[3][0], a3, w0.x); fma2(acc[3][1], a3, w0.y);
                    fma2(acc[3][2], a3, w1.x); fma2(acc[3][3], a3, w1.y);
                }
            }
            __syncwarp();
            {
                const int mr[4] = {mr0, mr1, mr2, mr3};
#pragma unroll
                for (int mi = 0; mi < 4; mi++)
#pragma unroll
                    for (int np = 0; np < 4; np++) {
                        float2 f = unp(acc[mi][np]);
                        int n = ng * 8 + np * 2;
                        Abuf[n * 66 + mr[mi]] = f.x;
                        Abuf[(n + 1) * 66 + mr[mi]] = f.y;
                    }
            }
            __syncthreads();
#pragma unroll
            for (int j = 0; j < 2; j++) {
                int idx = tid + 512 * j;
                int nl = idx & 15, m = idx >> 4;
                float s = (j == 0) ? b2v0 : b2v1;
#pragma unroll
                for (int w = 0; w < 16; w++) s += Rall[w * PWS + nl * 66 + m];
                __stcg(&g_cont[m * (4 * DD) + nB0 + nl], s);
            }
        }
        gbar(&barc);

        // ---------- phase C: gates + LN + state update (blocks 0..63) ----------
        if (b < NN) {
            float mval = mask[(size_t)b * SS + t];
            const float* cb = g_cont + b * (4 * DD);
            float c0 = __ldcg(cb + tid);
            float c1 = __ldcg(cb + 512 + tid);
            float c2 = __ldcg(cb + 1024 + tid);
            float c3 = __ldcg(cb + 1536 + tid);
            float x0 = g_X[((size_t)b * SS + t) * DD + tid];
            float v = sigm(c0) * hr + sigm(c1) * x0 + sigm(c2) * c3;
            float mean = bsum512(v, scC) * (1.f / DD);
            float e = v - mean;
            float var = bsum512(e * e, scC) * (1.f / DD);
            float rs = rsqrtf(var + 1e-5f);
            float hn = e * rs * lngv + lnbv;
            hr = hn;
            g_ht[b * DD + tid] = hn;
            out[((size_t)b * SS + t) * DD + tid] = hn * mval;
            gsr = mval * hn + (1.f - mval) * gsr;
        }
        gbar(&barc);
    }

    // final global_state
    if (b < NN) {
        out[(size_t)NN * SS * DD + b * DD + tid] = gsr;
    }
}

extern "C" void kernel_launch(void* const* d_in, const int* in_sizes, int n_in,
                              void* d_out, int out_size) {
    (void)in_sizes; (void)n_in; (void)out_size;
    const float* seq   = (const float*)d_in[0];
    const float* mask  = (const float*)d_in[1];
    const float* START = (const float*)d_in[2];
    const float* Wi    = (const float*)d_in[3];
    const float* bi    = (const float*)d_in[4];
    const float* W1    = (const float*)d_in[5];
    const float* b1    = (const float*)d_in[6];
    const float* W2    = (const float*)d_in[7];
    const float* b2    = (const float*)d_in[8];
    const float* lng   = (const float*)d_in[9];
    const float* lnb   = (const float*)d_in[10];
    float* out = (float*)d_out;

    static bool attr_done = false;
    if (!attr_done) {
        cudaFuncSetAttribute(k_main, cudaFuncAttributeMaxDynamicSharedMemorySize,
                             SMEM_MAIN);
        attr_done = true;
    }

    k_reset<<<1, 64>>>();
    k_main<<<GRID, NTHREADS, SMEM_MAIN>>>(seq, mask, START, Wi, bi,
                                          W1, b1, W2, b2, lng, lnb, out);
}